// round 15
// baseline (speedup 1.0000x reference)
#include <cuda_runtime.h>
#include <cstdint>

#define HID 64
#define H2  128
#define NSEG 64
#define CH 1024
#define MAXN 50048
#define MAXT 1600512
#define MAXCHUNKS 1600
#define WAVES 5
#define SCAP 33280   // per-seg smem words = 133120 B (seg mean 32010, sigma~177)

// ---------------- device scratch ----------------
__device__ float g_P[MAXN * H2];                 // 25.6 MB  h @ W1[:64,:] + 0.5*b1
__device__ unsigned long long g_pack[MAXT];      // src | dst<<16 | conn<<32 | seg<<33
__device__ unsigned g_ulog[MAXT];                // order-preserving uint32 logits
__device__ int g_histT[NSEG * MAXCHUNKS];        // [seg][chunk]
__device__ int g_posCnt[NSEG];                   // reset inside k_solve each replay
__device__ int g_segCnt[NSEG];                   // reset inside k_solve each replay
__device__ int g_segStart[NSEG];

__device__ __forceinline__ float unflip(unsigned u) {
    unsigned fb = (u & 0x80000000u) ? (u ^ 0x80000000u) : ~u;
    return __uint_as_float(fb);
}

// un-hoistable L1-cached vector load (keeps constants out of long-lived registers)
#define LD4(v, p, off) \
    asm volatile("ld.global.nc.v4.f32 {%0,%1,%2,%3}, [%4+" #off "];" \
                 : "=f"((v).x), "=f"((v).y), "=f"((v).z), "=f"((v).w) : "l"(p))

// ---------------- static stream/event glue (created at load, outside capture) ----
namespace {
struct Glue {
    cudaStream_t sB;
    cudaEvent_t evFork, evGemm;
    Glue() {
        cudaStreamCreateWithFlags(&sB, cudaStreamNonBlocking);
        cudaEventCreateWithFlags(&evFork, cudaEventDisableTiming);
        cudaEventCreateWithFlags(&evGemm, cudaEventDisableTiming);
    }
};
Glue g_glue;
}

// ---------------- per-chunk seg histograms + seg totals ----------------
__global__ __launch_bounds__(256) void k_hist(const int* __restrict__ pos,
                                              const int* __restrict__ neg,
                                              const int* __restrict__ nb, int E, int T) {
    __shared__ int sh[NSEG];
    __shared__ int shp[NSEG];
    int tid = threadIdx.x;
    if (tid < NSEG) { sh[tid] = 0; shp[tid] = 0; }
    __syncthreads();
    int base = blockIdx.x * CH;
    for (int i = tid; i < CH; i += 256) {
        int e = base + i;
        if (e < T) {
            int src = (e < E) ? pos[e] : neg[e - E];
            int s = nb[src];
            atomicAdd(&sh[s], 1);
            if (e < E) atomicAdd(&shp[s], 1);
        }
    }
    __syncthreads();
    if (tid < NSEG) {
        g_histT[tid * MAXCHUNKS + blockIdx.x] = sh[tid];
        if (shp[tid]) atomicAdd(&g_posCnt[tid], shp[tid]);
        if (sh[tid]) atomicAdd(&g_segCnt[tid], sh[tid]);
    }
}

// ---------------- P = h @ W1[:64,:] + 0.5*b1 (runs on side stream) ----------------
__global__ __launch_bounds__(256) void k_gemmP(const float* __restrict__ h,
                                               const float* __restrict__ W1,
                                               const float* __restrict__ b1, int N) {
    __shared__ float Ws[HID][H2];
    int tid = threadIdx.x;
    for (int i = tid; i < HID * H2; i += 256) Ws[i / H2][i % H2] = W1[i];
    __syncthreads();
    int w = tid >> 5, lane = tid & 31;
    int j = lane * 4;
    float4 hb = *(const float4*)&b1[j];
    float4 binit = make_float4(0.5f * hb.x, 0.5f * hb.y, 0.5f * hb.z, 0.5f * hb.w);
    int totalWarps = gridDim.x * 8;
    for (int n0 = (blockIdx.x * 8 + w) * 8; n0 < N; n0 += totalWarps * 8) {
        float h0[8], h1v[8];
#pragma unroll
        for (int m = 0; m < 8; m++) {
            int nm = n0 + m;
            if (nm < N) { h0[m] = h[nm * HID + lane]; h1v[m] = h[nm * HID + 32 + lane]; }
            else { h0[m] = 0.f; h1v[m] = 0.f; }
        }
        float4 acc[8];
#pragma unroll
        for (int m = 0; m < 8; m++) acc[m] = binit;
#pragma unroll
        for (int k = 0; k < 64; k++) {
            float4 wv = *(const float4*)&Ws[k][j];
#pragma unroll
            for (int m = 0; m < 8; m++) {
                float hv = __shfl_sync(0xffffffffu, (k < 32) ? h0[m] : h1v[m], k & 31);
                acc[m].x += hv * wv.x; acc[m].y += hv * wv.y;
                acc[m].z += hv * wv.z; acc[m].w += hv * wv.w;
            }
        }
#pragma unroll
        for (int m = 0; m < 8; m++)
            if (n0 + m < N) *(float4*)&g_P[(n0 + m) * H2 + j] = acc[m];
    }
}

// ---------------- per-seg chunk prefix + zero node-mask ----------------
__global__ __launch_bounds__(256) void k_scanC(int numChunks, float* outNM, int N) {
    __shared__ int sh[256];
    __shared__ int segc[NSEG];
    __shared__ int s_start;
    int s = blockIdx.x;
    int tid = threadIdx.x;
    for (int i = s * 256 + tid; i < N; i += NSEG * 256) outNM[i] = 0.0f;
    if (tid < NSEG) segc[tid] = g_segCnt[tid];
    __syncthreads();
    if (tid == 0) {
        int acc = 0;
        for (int i = 0; i < s; i++) acc += segc[i];
        s_start = acc;
        g_segStart[s] = acc;
    }
    int q = (numChunks + 255) / 256;
    int c0 = tid * q;
    int c1 = min(numChunks, c0 + q);
    int mySum = 0;
    for (int c = c0; c < c1; c++) mySum += g_histT[s * MAXCHUNKS + c];
    sh[tid] = mySum;
    __syncthreads();
    for (int off = 1; off < 256; off <<= 1) {
        int v = (tid >= off) ? sh[tid - off] : 0;
        __syncthreads();
        sh[tid] += v;
        __syncthreads();
    }
    int off = s_start + sh[tid] - mySum;
    for (int c = c0; c < c1; c++) {
        int v = g_histT[s * MAXCHUNKS + c];
        g_histT[s * MAXCHUNKS + c] = off;
        off += v;
    }
}

// ---------------- stable counting-sort scatter ----------------
__global__ __launch_bounds__(256) void k_scatter(const int* __restrict__ pos,
                                                 const int* __restrict__ neg,
                                                 const int* __restrict__ nb, int E, int T) {
    __shared__ int cnt[NSEG];
    __shared__ int wcnt[8][NSEG];
    int tid = threadIdx.x, w = tid >> 5, lane = tid & 31;
    int chunk = blockIdx.x;
    if (tid < NSEG) cnt[tid] = g_histT[tid * MAXCHUNKS + chunk];
#pragma unroll
    for (int r = 0; r < CH / 256; r++) {
        int e = chunk * CH + r * 256 + tid;
        bool valid = e < T;
        int seg = 0;
        unsigned long long pk = 0;
        if (valid) {
            int src, dst;
            if (e < E) { src = pos[e]; dst = pos[E + e]; }
            else       { src = neg[e - E]; dst = neg[E + (e - E)]; }
            seg = nb[src];
            pk = (unsigned long long)(unsigned)src
               | ((unsigned long long)(unsigned)dst << 16)
               | ((unsigned long long)(e < E ? 1u : 0u) << 32)
               | ((unsigned long long)(unsigned)seg << 33);
        }
        for (int i = tid; i < 8 * NSEG; i += 256) ((int*)wcnt)[i] = 0;
        __syncthreads();
        unsigned m = __match_any_sync(0xffffffffu, valid ? seg : (256 + lane));
        int rank = __popc(m & ((1u << lane) - 1u));
        if (valid && rank == 0) wcnt[w][seg] = __popc(m);
        __syncthreads();
        if (tid < NSEG) {
            int acc = cnt[tid];
#pragma unroll
            for (int ww = 0; ww < 8; ww++) {
                int v = wcnt[ww][tid];
                wcnt[ww][tid] = acc;
                acc += v;
            }
            cnt[tid] = acc;
        }
        __syncthreads();
        if (valid) g_pack[wcnt[w][seg] + rank] = pk;
        __syncthreads();
    }
}

// ---------------- MLP: 2 edges/warp, constants reloaded in-loop, 5 blocks/SM ----------------
__global__ __launch_bounds__(256, 5) void k_mlp(const float* __restrict__ W1,
                                                const float* __restrict__ lng,
                                                const float* __restrict__ lnb,
                                                const float* __restrict__ W2,
                                                const float* __restrict__ b2,
                                                int T, int MT) {
    int bid = blockIdx.x;
    int tile = (bid % 148) * WAVES + (bid / 148);
    int start = tile * MT;
    if (start >= T) return;
    int end = min(T, start + MT);
    int lane = threadIdx.x & 31;
    int half = lane >> 4, hl = lane & 15;
    int w = threadIdx.x >> 5;
    const float* WLp = W1 + 64 * H2 + hl * 4;
    const float* LGp = lng + hl * 4;
    const float* LBp = lnb + hl * 4;
    const float* W2p = W2 + hl * 4;
    float b2v = b2[0];
    int t2 = start + w * 2;
    if (t2 >= end) return;
    unsigned long long pk = __ldcs(&g_pack[t2 + half]);
    for (; t2 < end; ) {
        int t = t2 + half;
        int src = (int)(pk & 0xffffull);
        int dst = (int)((pk >> 16) & 0xffffull);
        float conn = (float)((pk >> 32) & 1ull);
        const float4* ps = (const float4*)&g_P[src * H2];
        const float4* pd = (const float4*)&g_P[dst * H2];
        float4 a0 = ps[hl], a1 = ps[16 + hl];
        float4 c0 = pd[hl], c1 = pd[16 + hl];
        int t2n = t2 + 16;
        unsigned long long pkn = 0;
        if (t2n < end) pkn = __ldcs(&g_pack[t2n + half]);
        float4 wL0, wL1;
        LD4(wL0, WLp, 0);
        LD4(wL1, WLp, 256);
        float x0 = a0.x + c0.x + conn * wL0.x;
        float x1 = a0.y + c0.y + conn * wL0.y;
        float x2 = a0.z + c0.z + conn * wL0.z;
        float x3 = a0.w + c0.w + conn * wL0.w;
        float x4 = a1.x + c1.x + conn * wL1.x;
        float x5 = a1.y + c1.y + conn * wL1.y;
        float x6 = a1.z + c1.z + conn * wL1.z;
        float x7 = a1.w + c1.w + conn * wL1.w;
        float s = x0 + x1 + x2 + x3 + x4 + x5 + x6 + x7;
        float q = x0*x0 + x1*x1 + x2*x2 + x3*x3 + x4*x4 + x5*x5 + x6*x6 + x7*x7;
        // issue late-use constant loads before the shuffle chains (L1 hits)
        float4 g0, g1, e0, e1, w20, w21;
        LD4(g0, LGp, 0);
        LD4(g1, LGp, 256);
        LD4(e0, LBp, 0);
        LD4(e1, LBp, 256);
        LD4(w20, W2p, 0);
        LD4(w21, W2p, 256);
#pragma unroll
        for (int o = 8; o; o >>= 1) {
            s += __shfl_xor_sync(0xffffffffu, s, o);
            q += __shfl_xor_sync(0xffffffffu, q, o);
        }
        float mu = s * (1.0f / 128.0f);
        float var = q * (1.0f / 128.0f) - mu * mu;
        float rs = rsqrtf(var + 1e-5f);
        float p =
          fmaxf((x0 - mu) * rs * g0.x + e0.x, 0.0f) * w20.x
        + fmaxf((x1 - mu) * rs * g0.y + e0.y, 0.0f) * w20.y
        + fmaxf((x2 - mu) * rs * g0.z + e0.z, 0.0f) * w20.z
        + fmaxf((x3 - mu) * rs * g0.w + e0.w, 0.0f) * w20.w
        + fmaxf((x4 - mu) * rs * g1.x + e1.x, 0.0f) * w21.x
        + fmaxf((x5 - mu) * rs * g1.y + e1.y, 0.0f) * w21.y
        + fmaxf((x6 - mu) * rs * g1.z + e1.z, 0.0f) * w21.z
        + fmaxf((x7 - mu) * rs * g1.w + e1.w, 0.0f) * w21.w;
#pragma unroll
        for (int o = 8; o; o >>= 1) p += __shfl_xor_sync(0xffffffffu, p, o);
        if (hl == 0) {
            float logit = p + b2v;
            unsigned u = __float_as_uint(logit);
            u ^= (u & 0x80000000u) ? 0xffffffffu : 0x80000000u;
            __stcs(&g_ulog[t], u);
        }
        pk = pkn;
        t2 = t2n;
    }
}

// ---------------- exact select: 8-bit radix, pass-0 hist fused into copy ----------------
__global__ __launch_bounds__(1024) void k_solve(float* __restrict__ outMask,
                                                float* __restrict__ outW,
                                                float* __restrict__ outNM) {
    extern __shared__ unsigned sarr[];
    __shared__ int wh[32][256];
    __shared__ int ss[256];
    __shared__ int cscan[1024];
    __shared__ unsigned s_pref;
    __shared__ int s_kn;
    int g = blockIdx.x;
    int tid = threadIdx.x, w = tid >> 5;
    // snapshot BEFORE resetting
    int cnt = g_segCnt[g], start = g_segStart[g];
    int pc = g_posCnt[g];
    __syncthreads();
    if (tid == 0) { g_posCnt[g] = 0; g_segCnt[g] = 0; }   // reset for next replay
    if (cnt <= 0) return;
    int k = (int)floorf(__int2float_rn(pc) * 0.9f);
    if (k > cnt) k = cnt;
    for (int i = tid; i < 32 * 256; i += 1024) ((int*)wh)[i] = 0;
    __syncthreads();
    bool inS = (cnt <= SCAP);
    const unsigned* arr;
    if (inS) {
        for (int i = tid; i < cnt; i += 1024) {
            unsigned u = g_ulog[start + i];
            sarr[i] = u;
            atomicAdd(&wh[w][u >> 24], 1);
        }
        arr = sarr;
    } else {
        for (int i = tid; i < cnt; i += 1024)
            atomicAdd(&wh[w][g_ulog[start + i] >> 24], 1);
        arr = &g_ulog[start];
    }
    __syncthreads();
    unsigned pref = 0;
    int kneed = k;
    if (k > 0) {
        for (int p = 0; p < 4; p++) {
            int shift = 24 - 8 * p;
            if (p > 0) {
                unsigned hiMask = 0xffffffffu << (shift + 8);
                for (int i = tid; i < 32 * 256; i += 1024) ((int*)wh)[i] = 0;
                __syncthreads();
                for (int i = tid; i < cnt; i += 1024) {
                    unsigned u = arr[i];
                    if ((u & hiMask) == pref) atomicAdd(&wh[w][(u >> shift) & 255], 1);
                }
                __syncthreads();
            }
            if (tid < 256) {
                int tot = 0;
#pragma unroll
                for (int ww = 0; ww < 32; ww++) tot += wh[ww][tid];
                ss[tid] = tot;
            }
            __syncthreads();
            for (int off = 1; off < 256; off <<= 1) {
                int v = 0;
                if (tid < 256 && tid + off < 256) v = ss[tid + off];
                __syncthreads();
                if (tid < 256) ss[tid] += v;
                __syncthreads();
            }
            if (tid < 256) {
                int nxt = (tid == 255) ? 0 : ss[tid + 1];
                if (ss[tid] >= kneed && nxt < kneed) {
                    s_pref = pref | ((unsigned)tid << shift);
                    s_kn = kneed - nxt;
                }
            }
            __syncthreads();
            pref = s_pref;
            kneed = s_kn;
            __syncthreads();
        }
    } else {
        pref = 0xffffffffu;
        kneed = 0;
    }
    // phase 1: stable eq tie-break (per-thread contiguous ranges; few eq elements)
    float wv = unflip(pref);
    int L = (cnt + 1023) / 1024;
    int lo = tid * L, hi = min(cnt, lo + L);
    int c = 0;
    for (int i = lo; i < hi; i++) if (arr[i] == pref) c++;
    cscan[tid] = c;
    __syncthreads();
    for (int off = 1; off < 1024; off <<= 1) {
        int v = (tid >= off) ? cscan[tid - off] : 0;
        __syncthreads();
        cscan[tid] += v;
        __syncthreads();
    }
    int r = cscan[tid] - c;
    if (c > 0) {
        for (int i = lo; i < hi; i++) {
            if (arr[i] == pref) {
                bool sel = r < kneed;
                int t = start + i;
                outMask[t] = sel ? 1.0f : 0.0f;
                if (sel) {
                    outW[t] = wv;
                    unsigned long long pk = g_pack[t];
                    outNM[(int)(pk & 0xffffull)] = 1.0f;
                    outNM[(int)((pk >> 16) & 0xffffull)] = 1.0f;
                } else {
                    outW[t] = 0.0f;
                }
                r++;
            }
        }
    }
    // phase 2: non-eq outputs, strided (coalesced)
    for (int i = tid; i < cnt; i += 1024) {
        unsigned u = arr[i];
        if (u == pref) continue;
        bool gt = u > pref;
        int t = start + i;
        outMask[t] = gt ? 1.0f : 0.0f;
        if (gt) {
            outW[t] = unflip(u);
            unsigned long long pk = g_pack[t];
            outNM[(int)(pk & 0xffffull)] = 1.0f;
            outNM[(int)((pk >> 16) & 0xffffull)] = 1.0f;
        } else {
            outW[t] = 0.0f;
        }
    }
}

// ---------------- launch: fork gemm onto side stream, join before mlp ----------------
extern "C" void kernel_launch(void* const* d_in, const int* in_sizes, int n_in,
                              void* d_out, int out_size) {
    const float* h   = (const float*)d_in[0];
    const float* W1  = (const float*)d_in[1];
    const float* b1  = (const float*)d_in[2];
    const float* lng = (const float*)d_in[3];
    const float* lnb = (const float*)d_in[4];
    const float* W2  = (const float*)d_in[5];
    const float* b2  = (const float*)d_in[6];
    const int* pos   = (const int*)d_in[7];
    const int* neg   = (const int*)d_in[8];
    const int* nb    = (const int*)d_in[9];

    int N = in_sizes[9];
    int E = in_sizes[7] / 2;
    int T = 2 * E;
    int numChunks = (T + CH - 1) / CH;

    float* outMask = (float*)d_out;
    float* outW    = outMask + T;
    float* outNM   = outW + T;

    int mlpGrid = 148 * WAVES;
    int MT = ((T + mlpGrid - 1) / mlpGrid + 31) & ~31;

    cudaFuncSetAttribute(k_solve, cudaFuncAttributeMaxDynamicSharedMemorySize, SCAP * 4);

    // fork: gemm on side stream, concurrently with hist/scan/scatter on main stream
    cudaEventRecord(g_glue.evFork, 0);
    cudaStreamWaitEvent(g_glue.sB, g_glue.evFork, 0);
    k_gemmP<<<296, 256, 0, g_glue.sB>>>(h, W1, b1, N);
    cudaEventRecord(g_glue.evGemm, g_glue.sB);

    k_hist<<<numChunks, 256>>>(pos, neg, nb, E, T);
    k_scanC<<<NSEG, 256>>>(numChunks, outNM, N);
    k_scatter<<<numChunks, 256>>>(pos, neg, nb, E, T);

    // join: mlp needs both scatter (main) and gemm (side)
    cudaStreamWaitEvent(0, g_glue.evGemm, 0);
    k_mlp<<<mlpGrid, 256>>>(W1, lng, lnb, W2, b2, T, MT);   // 4th launch -> profiled
    k_solve<<<NSEG, 1024, SCAP * 4>>>(outMask, outW, outNM);
    (void)n_in; (void)out_size;
}

// round 16
// speedup vs baseline: 1.4432x; 1.4432x over previous
#include <cuda_runtime.h>
#include <cstdint>

#define HID 64
#define H2  128
#define NSEG 64
#define CH 1024
#define MAXN 50048
#define MAXT 1600512
#define MAXCHUNKS 1600
#define WAVES 4
#define SCAP 33280   // per-seg smem words = 133120 B (seg mean 32010, sigma~177)

// ---------------- device scratch ----------------
__device__ float g_P[MAXN * H2];                 // 25.6 MB  h @ W1[:64,:] + 0.5*b1
__device__ unsigned long long g_pack[MAXT];      // src | dst<<16 | conn<<32 | seg<<33
__device__ unsigned g_ulog[MAXT];                // order-preserving uint32 logits
__device__ int g_histT[NSEG * MAXCHUNKS];        // [seg][chunk]
__device__ int g_posCnt[NSEG];                   // reset inside k_solve each replay
__device__ int g_segCnt[NSEG];                   // reset inside k_solve each replay
__device__ int g_segStart[NSEG];

__device__ __forceinline__ float unflip(unsigned u) {
    unsigned fb = (u & 0x80000000u) ? (u ^ 0x80000000u) : ~u;
    return __uint_as_float(fb);
}

// ---------------- static stream/event glue (created at load, outside capture) ----
namespace {
struct Glue {
    cudaStream_t sB;
    cudaEvent_t evFork, evGemm;
    Glue() {
        cudaStreamCreateWithFlags(&sB, cudaStreamNonBlocking);
        cudaEventCreateWithFlags(&evFork, cudaEventDisableTiming);
        cudaEventCreateWithFlags(&evGemm, cudaEventDisableTiming);
    }
};
Glue g_glue;
}

// ---------------- per-chunk seg histograms + seg totals ----------------
__global__ __launch_bounds__(256) void k_hist(const int* __restrict__ pos,
                                              const int* __restrict__ neg,
                                              const int* __restrict__ nb, int E, int T) {
    __shared__ int sh[NSEG];
    __shared__ int shp[NSEG];
    int tid = threadIdx.x;
    if (tid < NSEG) { sh[tid] = 0; shp[tid] = 0; }
    __syncthreads();
    int base = blockIdx.x * CH;
    for (int i = tid; i < CH; i += 256) {
        int e = base + i;
        if (e < T) {
            int src = (e < E) ? pos[e] : neg[e - E];
            int s = nb[src];
            atomicAdd(&sh[s], 1);
            if (e < E) atomicAdd(&shp[s], 1);
        }
    }
    __syncthreads();
    if (tid < NSEG) {
        g_histT[tid * MAXCHUNKS + blockIdx.x] = sh[tid];
        if (shp[tid]) atomicAdd(&g_posCnt[tid], shp[tid]);
        if (sh[tid]) atomicAdd(&g_segCnt[tid], sh[tid]);
    }
}

// ---------------- P = h @ W1[:64,:] + 0.5*b1 (runs on side stream) ----------------
__global__ __launch_bounds__(256) void k_gemmP(const float* __restrict__ h,
                                               const float* __restrict__ W1,
                                               const float* __restrict__ b1, int N) {
    __shared__ float Ws[HID][H2];
    int tid = threadIdx.x;
    for (int i = tid; i < HID * H2; i += 256) Ws[i / H2][i % H2] = W1[i];
    __syncthreads();
    int w = tid >> 5, lane = tid & 31;
    int j = lane * 4;
    float4 hb = *(const float4*)&b1[j];
    float4 binit = make_float4(0.5f * hb.x, 0.5f * hb.y, 0.5f * hb.z, 0.5f * hb.w);
    int totalWarps = gridDim.x * 8;
    for (int n0 = (blockIdx.x * 8 + w) * 8; n0 < N; n0 += totalWarps * 8) {
        float h0[8], h1v[8];
#pragma unroll
        for (int m = 0; m < 8; m++) {
            int nm = n0 + m;
            if (nm < N) { h0[m] = h[nm * HID + lane]; h1v[m] = h[nm * HID + 32 + lane]; }
            else { h0[m] = 0.f; h1v[m] = 0.f; }
        }
        float4 acc[8];
#pragma unroll
        for (int m = 0; m < 8; m++) acc[m] = binit;
#pragma unroll
        for (int k = 0; k < 64; k++) {
            float4 wv = *(const float4*)&Ws[k][j];
#pragma unroll
            for (int m = 0; m < 8; m++) {
                float hv = __shfl_sync(0xffffffffu, (k < 32) ? h0[m] : h1v[m], k & 31);
                acc[m].x += hv * wv.x; acc[m].y += hv * wv.y;
                acc[m].z += hv * wv.z; acc[m].w += hv * wv.w;
            }
        }
#pragma unroll
        for (int m = 0; m < 8; m++)
            if (n0 + m < N) *(float4*)&g_P[(n0 + m) * H2 + j] = acc[m];
    }
}

// ---------------- per-seg chunk prefix + zero node-mask ----------------
__global__ __launch_bounds__(256) void k_scanC(int numChunks, float* outNM, int N) {
    __shared__ int sh[256];
    __shared__ int segc[NSEG];
    __shared__ int s_start;
    int s = blockIdx.x;
    int tid = threadIdx.x;
    for (int i = s * 256 + tid; i < N; i += NSEG * 256) outNM[i] = 0.0f;
    if (tid < NSEG) segc[tid] = g_segCnt[tid];
    __syncthreads();
    if (tid == 0) {
        int acc = 0;
        for (int i = 0; i < s; i++) acc += segc[i];
        s_start = acc;
        g_segStart[s] = acc;
    }
    int q = (numChunks + 255) / 256;
    int c0 = tid * q;
    int c1 = min(numChunks, c0 + q);
    int mySum = 0;
    for (int c = c0; c < c1; c++) mySum += g_histT[s * MAXCHUNKS + c];
    sh[tid] = mySum;
    __syncthreads();
    for (int off = 1; off < 256; off <<= 1) {
        int v = (tid >= off) ? sh[tid - off] : 0;
        __syncthreads();
        sh[tid] += v;
        __syncthreads();
    }
    int off = s_start + sh[tid] - mySum;
    for (int c = c0; c < c1; c++) {
        int v = g_histT[s * MAXCHUNKS + c];
        g_histT[s * MAXCHUNKS + c] = off;
        off += v;
    }
}

// ---------------- stable counting-sort scatter ----------------
__global__ __launch_bounds__(256) void k_scatter(const int* __restrict__ pos,
                                                 const int* __restrict__ neg,
                                                 const int* __restrict__ nb, int E, int T) {
    __shared__ int cnt[NSEG];
    __shared__ int wcnt[8][NSEG];
    int tid = threadIdx.x, w = tid >> 5, lane = tid & 31;
    int chunk = blockIdx.x;
    if (tid < NSEG) cnt[tid] = g_histT[tid * MAXCHUNKS + chunk];
#pragma unroll
    for (int r = 0; r < CH / 256; r++) {
        int e = chunk * CH + r * 256 + tid;
        bool valid = e < T;
        int seg = 0;
        unsigned long long pk = 0;
        if (valid) {
            int src, dst;
            if (e < E) { src = pos[e]; dst = pos[E + e]; }
            else       { src = neg[e - E]; dst = neg[E + (e - E)]; }
            seg = nb[src];
            pk = (unsigned long long)(unsigned)src
               | ((unsigned long long)(unsigned)dst << 16)
               | ((unsigned long long)(e < E ? 1u : 0u) << 32)
               | ((unsigned long long)(unsigned)seg << 33);
        }
        for (int i = tid; i < 8 * NSEG; i += 256) ((int*)wcnt)[i] = 0;
        __syncthreads();
        unsigned m = __match_any_sync(0xffffffffu, valid ? seg : (256 + lane));
        int rank = __popc(m & ((1u << lane) - 1u));
        if (valid && rank == 0) wcnt[w][seg] = __popc(m);
        __syncthreads();
        if (tid < NSEG) {
            int acc = cnt[tid];
#pragma unroll
            for (int ww = 0; ww < 8; ww++) {
                int v = wcnt[ww][tid];
                wcnt[ww][tid] = acc;
                acc += v;
            }
            cnt[tid] = acc;
        }
        __syncthreads();
        if (valid) g_pack[wcnt[w][seg] + rank] = pk;
        __syncthreads();
    }
}

// ---------------- MLP: 2 edges/warp, streaming hints + pk prefetch ----------------
__global__ __launch_bounds__(256, 4) void k_mlp(const float* __restrict__ W1,
                                                const float* __restrict__ lng,
                                                const float* __restrict__ lnb,
                                                const float* __restrict__ W2,
                                                const float* __restrict__ b2,
                                                int T, int MT) {
    int bid = blockIdx.x;
    int tile = (bid % 148) * WAVES + (bid / 148);
    int start = tile * MT;
    if (start >= T) return;
    int end = min(T, start + MT);
    int lane = threadIdx.x & 31;
    int half = lane >> 4, hl = lane & 15;
    int w = threadIdx.x >> 5;
    const float4* WL = (const float4*)&W1[64 * H2];
    const float4* LG = (const float4*)lng;
    const float4* LB = (const float4*)lnb;
    const float4* W2v = (const float4*)W2;
    float4 wL0 = WL[hl],  wL1 = WL[16 + hl];
    float4 g0  = LG[hl],  g1  = LG[16 + hl];
    float4 e0  = LB[hl],  e1  = LB[16 + hl];
    float4 w20 = W2v[hl], w21 = W2v[16 + hl];
    float b2v = b2[0];
    int t2 = start + w * 2;
    if (t2 >= end) return;
    unsigned long long pk = __ldcs(&g_pack[t2 + half]);
    for (; t2 < end; ) {
        int t = t2 + half;
        int src = (int)(pk & 0xffffull);
        int dst = (int)((pk >> 16) & 0xffffull);
        float conn = (float)((pk >> 32) & 1ull);
        const float4* ps = (const float4*)&g_P[src * H2];
        const float4* pd = (const float4*)&g_P[dst * H2];
        float4 a0 = ps[hl], a1 = ps[16 + hl];
        float4 c0 = pd[hl], c1 = pd[16 + hl];
        int t2n = t2 + 16;
        unsigned long long pkn = 0;
        if (t2n < end) pkn = __ldcs(&g_pack[t2n + half]);
        float x0 = a0.x + c0.x + conn * wL0.x;
        float x1 = a0.y + c0.y + conn * wL0.y;
        float x2 = a0.z + c0.z + conn * wL0.z;
        float x3 = a0.w + c0.w + conn * wL0.w;
        float x4 = a1.x + c1.x + conn * wL1.x;
        float x5 = a1.y + c1.y + conn * wL1.y;
        float x6 = a1.z + c1.z + conn * wL1.z;
        float x7 = a1.w + c1.w + conn * wL1.w;
        float s = x0 + x1 + x2 + x3 + x4 + x5 + x6 + x7;
        float q = x0*x0 + x1*x1 + x2*x2 + x3*x3 + x4*x4 + x5*x5 + x6*x6 + x7*x7;
#pragma unroll
        for (int o = 8; o; o >>= 1) {
            s += __shfl_xor_sync(0xffffffffu, s, o);
            q += __shfl_xor_sync(0xffffffffu, q, o);
        }
        float mu = s * (1.0f / 128.0f);
        float var = q * (1.0f / 128.0f) - mu * mu;
        float rs = rsqrtf(var + 1e-5f);
        float p =
          fmaxf((x0 - mu) * rs * g0.x + e0.x, 0.0f) * w20.x
        + fmaxf((x1 - mu) * rs * g0.y + e0.y, 0.0f) * w20.y
        + fmaxf((x2 - mu) * rs * g0.z + e0.z, 0.0f) * w20.z
        + fmaxf((x3 - mu) * rs * g0.w + e0.w, 0.0f) * w20.w
        + fmaxf((x4 - mu) * rs * g1.x + e1.x, 0.0f) * w21.x
        + fmaxf((x5 - mu) * rs * g1.y + e1.y, 0.0f) * w21.y
        + fmaxf((x6 - mu) * rs * g1.z + e1.z, 0.0f) * w21.z
        + fmaxf((x7 - mu) * rs * g1.w + e1.w, 0.0f) * w21.w;
#pragma unroll
        for (int o = 8; o; o >>= 1) p += __shfl_xor_sync(0xffffffffu, p, o);
        if (hl == 0) {
            float logit = p + b2v;
            unsigned u = __float_as_uint(logit);
            u ^= (u & 0x80000000u) ? 0xffffffffu : 0x80000000u;
            __stcs(&g_ulog[t], u);
        }
        pk = pkn;
        t2 = t2n;
    }
}

// ---------------- exact select in smem + FULL finalize, 1024 threads ----------------
__global__ __launch_bounds__(1024) void k_solve(float* __restrict__ outMask,
                                                float* __restrict__ outW,
                                                float* __restrict__ outNM) {
    extern __shared__ unsigned sarr[];
    __shared__ int wh[32][256];
    __shared__ int ss[256];
    __shared__ int cscan[1024];
    __shared__ unsigned s_pref;
    __shared__ int s_kn;
    int g = blockIdx.x;
    int tid = threadIdx.x, w = tid >> 5;
    // snapshot BEFORE resetting
    int cnt = g_segCnt[g], start = g_segStart[g];
    int pc = g_posCnt[g];
    __syncthreads();
    if (tid == 0) { g_posCnt[g] = 0; g_segCnt[g] = 0; }   // reset for next replay
    if (cnt <= 0) return;
    int k = (int)floorf(__int2float_rn(pc) * 0.9f);
    if (k > cnt) k = cnt;
    const unsigned* arr;
    if (cnt <= SCAP) {
        for (int i = tid; i < cnt; i += 1024) sarr[i] = g_ulog[start + i];
        arr = sarr;
    } else {
        arr = &g_ulog[start];
    }
    __syncthreads();
    unsigned pref = 0;
    int kneed = k;
    if (k > 0) {
        for (int p = 0; p < 4; p++) {
            int shift = 24 - 8 * p;
            unsigned hiMask = (p == 0) ? 0u : (0xffffffffu << (shift + 8));
            for (int i = tid; i < 32 * 256; i += 1024) ((int*)wh)[i] = 0;
            __syncthreads();
            for (int i = tid; i < cnt; i += 1024) {
                unsigned u = arr[i];
                if ((u & hiMask) == pref) atomicAdd(&wh[w][(u >> shift) & 255], 1);
            }
            __syncthreads();
            if (tid < 256) {
                int tot = 0;
#pragma unroll
                for (int ww = 0; ww < 32; ww++) tot += wh[ww][tid];
                ss[tid] = tot;
            }
            __syncthreads();
            for (int off = 1; off < 256; off <<= 1) {
                int v = 0;
                if (tid < 256 && tid + off < 256) v = ss[tid + off];
                __syncthreads();
                if (tid < 256) ss[tid] += v;
                __syncthreads();
            }
            if (tid < 256) {
                int nxt = (tid == 255) ? 0 : ss[tid + 1];
                if (ss[tid] >= kneed && nxt < kneed) {
                    s_pref = pref | ((unsigned)tid << shift);
                    s_kn = kneed - nxt;
                }
            }
            __syncthreads();
            pref = s_pref;
            kneed = s_kn;
            __syncthreads();
        }
    } else {
        pref = 0xffffffffu;
        kneed = 0;
    }
    // phase 1: stable eq tie-break (per-thread contiguous ranges; few eq elements)
    float wv = unflip(pref);
    int L = (cnt + 1023) / 1024;
    int lo = tid * L, hi = min(cnt, lo + L);
    int c = 0;
    for (int i = lo; i < hi; i++) if (arr[i] == pref) c++;
    cscan[tid] = c;
    __syncthreads();
    for (int off = 1; off < 1024; off <<= 1) {
        int v = (tid >= off) ? cscan[tid - off] : 0;
        __syncthreads();
        cscan[tid] += v;
        __syncthreads();
    }
    int r = cscan[tid] - c;
    if (c > 0) {
        for (int i = lo; i < hi; i++) {
            if (arr[i] == pref) {
                bool sel = r < kneed;
                int t = start + i;
                outMask[t] = sel ? 1.0f : 0.0f;
                if (sel) {
                    outW[t] = wv;
                    unsigned long long pk = g_pack[t];
                    outNM[(int)(pk & 0xffffull)] = 1.0f;
                    outNM[(int)((pk >> 16) & 0xffffull)] = 1.0f;
                } else {
                    outW[t] = 0.0f;
                }
                r++;
            }
        }
    }
    // phase 2: non-eq outputs, strided (coalesced)
    for (int i = tid; i < cnt; i += 1024) {
        unsigned u = arr[i];
        if (u == pref) continue;
        bool gt = u > pref;
        int t = start + i;
        outMask[t] = gt ? 1.0f : 0.0f;
        if (gt) {
            outW[t] = unflip(u);
            unsigned long long pk = g_pack[t];
            outNM[(int)(pk & 0xffffull)] = 1.0f;
            outNM[(int)((pk >> 16) & 0xffffull)] = 1.0f;
        } else {
            outW[t] = 0.0f;
        }
    }
}

// ---------------- launch: fork gemm onto side stream, join before mlp ----------------
extern "C" void kernel_launch(void* const* d_in, const int* in_sizes, int n_in,
                              void* d_out, int out_size) {
    const float* h   = (const float*)d_in[0];
    const float* W1  = (const float*)d_in[1];
    const float* b1  = (const float*)d_in[2];
    const float* lng = (const float*)d_in[3];
    const float* lnb = (const float*)d_in[4];
    const float* W2  = (const float*)d_in[5];
    const float* b2  = (const float*)d_in[6];
    const int* pos   = (const int*)d_in[7];
    const int* neg   = (const int*)d_in[8];
    const int* nb    = (const int*)d_in[9];

    int N = in_sizes[9];
    int E = in_sizes[7] / 2;
    int T = 2 * E;
    int numChunks = (T + CH - 1) / CH;

    float* outMask = (float*)d_out;
    float* outW    = outMask + T;
    float* outNM   = outW + T;

    int mlpGrid = 148 * WAVES;
    int MT = ((T + mlpGrid - 1) / mlpGrid + 31) & ~31;

    cudaFuncSetAttribute(k_solve, cudaFuncAttributeMaxDynamicSharedMemorySize, SCAP * 4);

    // fork: gemm on side stream, concurrently with hist/scan/scatter on main stream
    cudaEventRecord(g_glue.evFork, 0);
    cudaStreamWaitEvent(g_glue.sB, g_glue.evFork, 0);
    k_gemmP<<<296, 256, 0, g_glue.sB>>>(h, W1, b1, N);
    cudaEventRecord(g_glue.evGemm, g_glue.sB);

    k_hist<<<numChunks, 256>>>(pos, neg, nb, E, T);
    k_scanC<<<NSEG, 256>>>(numChunks, outNM, N);
    k_scatter<<<numChunks, 256>>>(pos, neg, nb, E, T);

    // join: mlp needs both scatter (main) and gemm (side)
    cudaStreamWaitEvent(0, g_glue.evGemm, 0);
    k_mlp<<<mlpGrid, 256>>>(W1, lng, lnb, W2, b2, T, MT);
    k_solve<<<NSEG, 1024, SCAP * 4>>>(outMask, outW, outNM);
    (void)n_in; (void)out_size;
}